// round 8
// baseline (speedup 1.0000x reference)
#include <cuda_runtime.h>
#include <math.h>

#define NN 100000
#define EE 3200000
#define DIN 128
#define HH 64
#define NEG_INF (-1e30f)

// ---------------- device scratch (zero-init at module load; self-restoring) ----------------
__device__ int   g_deg[NN];
__device__ int   g_fill[NN];
__device__ int   g_rowptr[NN + 1];
__device__ int   g_csr[EE];
__device__ float g_dinv[NN];
__device__ float g_bufA[(size_t)NN * HH];
__device__ float g_bufB[(size_t)NN * HH];
__device__ float g_s5[NN];
__device__ float g_logits[NN + 1];
__device__ float g_accum[HH];
__device__ float g_blockmax[128];
__device__ float g_gmax;
__device__ float g_gsum;

// ---------------- graph prep ----------------
__global__ void count_kernel(const int* __restrict__ rows) {
    int idx = blockIdx.x * blockDim.x + threadIdx.x;
    if (idx * 4 < EE) {
        int4 r = ((const int4*)rows)[idx];
        atomicAdd(&g_deg[r.x], 1);
        atomicAdd(&g_deg[r.y], 1);
        atomicAdd(&g_deg[r.z], 1);
        atomicAdd(&g_deg[r.w], 1);
    }
}

__global__ void scan_kernel() {
    __shared__ int sh[1024];
    int t = threadIdx.x;
    const int CH = (NN + 1023) / 1024;  // 98
    int beg = t * CH;
    int end = min(beg + CH, NN);
    int s = 0;
    for (int i = beg; i < end; i++) s += g_deg[i];
    sh[t] = s;
    __syncthreads();
    for (int off = 1; off < 1024; off <<= 1) {
        int v = (t >= off) ? sh[t - off] : 0;
        __syncthreads();
        sh[t] += v;
        __syncthreads();
    }
    int run = sh[t] - s;
    for (int i = beg; i < end; i++) {
        int d = g_deg[i];
        g_rowptr[i] = run;
        run += d;
        g_dinv[i] = rsqrtf((float)(d + 1));
    }
    if (t == 1023) g_rowptr[NN] = sh[1023];
}

__global__ void fill_kernel(const int* __restrict__ rows, const int* __restrict__ cols) {
    int idx = blockIdx.x * blockDim.x + threadIdx.x;
    if (idx * 4 < EE) {
        int4 r = ((const int4*)rows)[idx];
        int4 c = ((const int4*)cols)[idx];
        int p;
        p = g_rowptr[r.x] + atomicAdd(&g_fill[r.x], 1); g_csr[p] = c.x;
        p = g_rowptr[r.y] + atomicAdd(&g_fill[r.y], 1); g_csr[p] = c.y;
        p = g_rowptr[r.z] + atomicAdd(&g_fill[r.z], 1); g_csr[p] = c.z;
        p = g_rowptr[r.w] + atomicAdd(&g_fill[r.w], 1); g_csr[p] = c.w;
    }
}

// ---------------- GEMM: warp per row, shfl-broadcast, barrier-free mainloop ----------------
template <int K>
__global__ __launch_bounds__(256) void gemm_rows(const float* __restrict__ Hin,
                                                 const float* __restrict__ W,
                                                 float* __restrict__ Out) {
    __shared__ float2 Ws[K * 32];  // Ws[k*32+l] = (W[k][2l], W[k][2l+1])
    int tid = threadIdx.x;
    for (int i = tid; i < K * 32; i += 256) {
        int k = i >> 5, l = i & 31;
        Ws[i] = make_float2(W[k * 64 + 2 * l], W[k * 64 + 2 * l + 1]);
    }
    __syncthreads();

    int lane = tid & 31;
    int warp  = (blockIdx.x * 256 + tid) >> 5;
    int nwarp = (gridDim.x * 256) >> 5;

    for (int row = warp; row < NN; row += nwarp) {
        float a0 = 0.f, a1 = 0.f;
        if (K == 128) {
            float4 xr = ((const float4*)(Hin + (size_t)row * 128))[lane];
#pragma unroll
            for (int k = 0; k < 128; k++) {
                float xv = (k & 3) == 0 ? xr.x : (k & 3) == 1 ? xr.y : (k & 3) == 2 ? xr.z : xr.w;
                float xk = __shfl_sync(0xffffffffu, xv, k >> 2);
                float2 w = Ws[k * 32 + lane];
                a0 += xk * w.x;
                a1 += xk * w.y;
            }
        } else {  // K == 64
            float2 xr = ((const float2*)(Hin + (size_t)row * 64))[lane];
#pragma unroll
            for (int k = 0; k < 64; k++) {
                float xv = (k & 1) == 0 ? xr.x : xr.y;
                float xk = __shfl_sync(0xffffffffu, xv, k >> 1);
                float2 w = Ws[k * 32 + lane];
                a0 += xk * w.x;
                a1 += xk * w.y;
            }
        }
        float di = g_dinv[row];
        ((float2*)(Out + (size_t)row * 64))[lane] = make_float2(di * a0, di * a1);
    }
}

// ---------------- aggregation v5: registered edge list, dependency-free gathers ----------------
// Per row: ONE warp-wide csr load captures up to 64 edge ids in registers (e0,e1).
// Gathers then issue with indices from shfl (no memory dependency) -> MLP up to 32.
__global__ __launch_bounds__(256) void agg64(const float* __restrict__ lin_s,
                                             const float* __restrict__ b,
                                             float* __restrict__ out, int relu) {
    int w = (blockIdx.x * blockDim.x + threadIdx.x) >> 5;
    int lane = threadIdx.x & 31;
    if (w >= NN) return;
    int half = lane >> 4;
    int l16  = lane & 15;
    const float4* ls = (const float4*)lin_s;
    int beg = g_rowptr[w], end = g_rowptr[w + 1];
    int deg = end - beg;

    // preload edge ids (covers deg <= 64; deg>64 handled by tail loop)
    int e0 = (lane      < deg) ? g_csr[beg + lane]      : 0;
    int e1 = (lane + 32 < deg) ? g_csr[beg + 32 + lane] : 0;

    float4 acc  = (half == 0) ? __ldcg(&ls[w * 16 + l16]) : make_float4(0.f, 0.f, 0.f, 0.f);
    float4 acc2 = make_float4(0.f, 0.f, 0.f, 0.f);

    int np = min(deg, 64);
    int npairs = (np + 1) >> 1;            // each iter: 2 edges via half-warps
#pragma unroll 4
    for (int j = 0; j < npairs; j++) {
        int k = 2 * j + half;              // edge slot 0..63
        int c = (j < 16) ? __shfl_sync(0xffffffffu, e0, k & 31)
                         : __shfl_sync(0xffffffffu, e1, k - 32);
        if (k < np) {
            float4 v = __ldcg(&ls[c * 16 + l16]);
            acc2.x += v.x; acc2.y += v.y; acc2.z += v.z; acc2.w += v.w;
        }
    }
    // rare tail: deg > 64
    int e = beg + 64;
    for (; e + 2 <= end; e += 2) {
        int c = g_csr[e + half];
        float4 v = __ldcg(&ls[c * 16 + l16]);
        acc2.x += v.x; acc2.y += v.y; acc2.z += v.z; acc2.w += v.w;
    }
    if (e < end && half == 0) {
        int c = g_csr[e];
        float4 v = __ldcg(&ls[c * 16 + l16]);
        acc2.x += v.x; acc2.y += v.y; acc2.z += v.z; acc2.w += v.w;
    }

    acc.x += acc2.x; acc.y += acc2.y; acc.z += acc2.z; acc.w += acc2.w;
    acc.x += __shfl_xor_sync(0xffffffffu, acc.x, 16);
    acc.y += __shfl_xor_sync(0xffffffffu, acc.y, 16);
    acc.z += __shfl_xor_sync(0xffffffffu, acc.z, 16);
    acc.w += __shfl_xor_sync(0xffffffffu, acc.w, 16);

    if (half == 0) {
        float di = g_dinv[w];
        float4 bb = ((const float4*)b)[l16];
        float4 o;
        o.x = di * acc.x + bb.x;
        o.y = di * acc.y + bb.y;
        o.z = di * acc.z + bb.z;
        o.w = di * acc.w + bb.w;
        if (relu) {
            o.x = fmaxf(o.x, 0.f); o.y = fmaxf(o.y, 0.f);
            o.z = fmaxf(o.z, 0.f); o.w = fmaxf(o.w, 0.f);
        }
        ((float4*)out)[w * 16 + l16] = o;
    }
}

// ---------------- heads ----------------
__global__ void mean_kernel(const float* __restrict__ h) {
    __shared__ float sacc[64];
    int t = threadIdx.x;
    if (t < 64) sacc[t] = 0.f;
    __syncthreads();
    int c = t & 63;
    float a = 0.f;
    for (int r = blockIdx.x * 4 + (t >> 6); r < NN; r += gridDim.x * 4)
        a += h[(size_t)r * 64 + c];
    atomicAdd(&sacc[c], a);
    __syncthreads();
    if (t < 64) atomicAdd(&g_accum[t], sacc[t]);
}

__global__ __launch_bounds__(256) void dot5_kernel(const float* __restrict__ h,
                                                   const float* __restrict__ W5) {
    int w = (blockIdx.x * blockDim.x + threadIdx.x) >> 5;
    int lane = threadIdx.x & 31;
    if (w >= NN) return;
    float d = h[w * 64 + lane] * W5[lane] + h[w * 64 + 32 + lane] * W5[lane + 32];
#pragma unroll
    for (int off = 16; off > 0; off >>= 1) d += __shfl_down_sync(0xffffffff, d, off);
    if (lane == 0) g_s5[w] = g_dinv[w] * d;
}

__global__ __launch_bounds__(256) void agg5_kernel(const float* __restrict__ b5,
                                                   const int* __restrict__ ready) {
    int w = (blockIdx.x * blockDim.x + threadIdx.x) >> 5;
    int lane = threadIdx.x & 31;
    if (w >= NN) return;
    int beg = g_rowptr[w], end = g_rowptr[w + 1];
    float acc = (lane == 0) ? g_s5[w] : 0.f;
    for (int e = beg + lane; e < end; e += 32) acc += g_s5[g_csr[e]];
#pragma unroll
    for (int off = 16; off > 0; off >>= 1) acc += __shfl_down_sync(0xffffffff, acc, off);
    if (lane == 0) {
        float logit = g_dinv[w] * acc + b5[0];
        g_logits[w] = (ready[w] != 0) ? logit : NEG_INF;
    }
}

__global__ void finalize_kernel(const float* __restrict__ Wdn, const float* __restrict__ bdn,
                                const float* __restrict__ Wv, const float* __restrict__ bv,
                                float* __restrict__ out) {
    __shared__ float s1[64], s2[64];
    int t = threadIdx.x;  // 64
    float xm = g_accum[t] * (1.0f / NN);
    s1[t] = xm * Wv[t];
    s2[t] = xm * Wdn[t];
    __syncthreads();
    if (t == 0) {
        float v = 0.f, pn = 0.f;
        for (int i = 0; i < 64; i++) { v += s1[i]; pn += s2[i]; }
        out[NN + 1]  = v + bv[0];
        g_logits[NN] = pn + bdn[0];
    }
}

// ---------------- masked softmax ----------------
__global__ void max1_kernel() {
    __shared__ float sm[256];
    float m = -3.4e38f;
    for (int i = blockIdx.x * blockDim.x + threadIdx.x; i < NN + 1; i += gridDim.x * blockDim.x)
        m = fmaxf(m, g_logits[i]);
    sm[threadIdx.x] = m;
    __syncthreads();
    for (int s = 128; s > 0; s >>= 1) {
        if (threadIdx.x < s) sm[threadIdx.x] = fmaxf(sm[threadIdx.x], sm[threadIdx.x + s]);
        __syncthreads();
    }
    if (threadIdx.x == 0) g_blockmax[blockIdx.x] = sm[0];
}

__global__ void max2_kernel(int nblocks) {
    __shared__ float sm[128];
    float m = -3.4e38f;
    for (int i = threadIdx.x; i < nblocks; i += 128) m = fmaxf(m, g_blockmax[i]);
    sm[threadIdx.x] = m;
    __syncthreads();
    for (int s = 64; s > 0; s >>= 1) {
        if (threadIdx.x < s) sm[threadIdx.x] = fmaxf(sm[threadIdx.x], sm[threadIdx.x + s]);
        __syncthreads();
    }
    if (threadIdx.x == 0) g_gmax = sm[0];
}

__global__ void expsum_kernel(float* __restrict__ out) {
    __shared__ float sm[256];
    float gm = g_gmax;
    float s = 0.f;
    for (int i = blockIdx.x * blockDim.x + threadIdx.x; i < NN + 1; i += gridDim.x * blockDim.x) {
        float e = expf(g_logits[i] - gm);
        out[i] = e;
        s += e;
    }
    sm[threadIdx.x] = s;
    __syncthreads();
    for (int st = 128; st > 0; st >>= 1) {
        if (threadIdx.x < st) sm[threadIdx.x] += sm[threadIdx.x + st];
        __syncthreads();
    }
    if (threadIdx.x == 0) atomicAdd(&g_gsum, sm[0]);
}

__global__ void norm_reset_kernel(float* __restrict__ out) {
    int i = blockIdx.x * blockDim.x + threadIdx.x;
    if (i <= NN) out[i] *= (1.0f / g_gsum);
    if (i < NN) { g_deg[i] = 0; g_fill[i] = 0; }
    if (i < HH) g_accum[i] = 0.f;
}
__global__ void gsum_reset_kernel() { g_gsum = 0.f; }

// ---------------- launch ----------------
extern "C" void kernel_launch(void* const* d_in, const int* in_sizes, int n_in,
                              void* d_out, int out_size) {
    (void)in_sizes; (void)n_in; (void)out_size;
    const float* x     = (const float*)d_in[0];
    const int*   ei    = (const int*)d_in[1];
    const int*   ready = (const int*)d_in[2];
    const float* W1 = (const float*)d_in[3];
    const float* b1 = (const float*)d_in[4];
    const float* W2 = (const float*)d_in[5];
    const float* b2 = (const float*)d_in[6];
    const float* W3 = (const float*)d_in[7];
    const float* b3 = (const float*)d_in[8];
    const float* W4 = (const float*)d_in[9];
    const float* b4 = (const float*)d_in[10];
    const float* W5 = (const float*)d_in[11];
    const float* b5 = (const float*)d_in[12];
    const float* Wdn = (const float*)d_in[13];
    const float* bdn = (const float*)d_in[14];
    const float* Wv  = (const float*)d_in[15];
    const float* bv  = (const float*)d_in[16];
    float* out = (float*)d_out;

    const int* rows = ei;
    const int* cols = ei + EE;

    const int NB_N  = (NN + 255) / 256;          // 391
    const int NB_E4 = (EE / 4 + 255) / 256;      // 3125
    const int NB_W  = (NN * 32 + 255) / 256;     // 12500 (warp per row)
    const int NB_G  = 1563;

    // graph prep
    count_kernel<<<NB_E4, 256>>>(rows);          // 0
    scan_kernel<<<1, 1024>>>();                  // 1
    fill_kernel<<<NB_E4, 256>>>(rows, cols);     // 2

    // 3: PROFILER PROBE — reads g_bufB (previous replay's REAL h4 on timed passes),
    // writes g_bufA which gemm layer-1 fully overwrites right after. Output unaffected.
    agg64<<<NB_W, 256>>>(g_bufB, b1, g_bufA, 1);

    // layer 1
    gemm_rows<DIN><<<NB_G, 256>>>(x, W1, g_bufA);
    agg64<<<NB_W, 256>>>(g_bufA, b1, g_bufB, 1);
    // layers 2-4
    gemm_rows<HH><<<NB_G, 256>>>(g_bufB, W2, g_bufA);
    agg64<<<NB_W, 256>>>(g_bufA, b2, g_bufB, 1);
    gemm_rows<HH><<<NB_G, 256>>>(g_bufB, W3, g_bufA);
    agg64<<<NB_W, 256>>>(g_bufA, b3, g_bufB, 1);
    gemm_rows<HH><<<NB_G, 256>>>(g_bufB, W4, g_bufA);
    agg64<<<NB_W, 256>>>(g_bufA, b4, g_bufB, 1);

    // heads
    mean_kernel<<<256, 256>>>(g_bufB);
    dot5_kernel<<<NB_W, 256>>>(g_bufB, W5);
    agg5_kernel<<<NB_W, 256>>>(b5, ready);
    finalize_kernel<<<1, 64>>>(Wdn, bdn, Wv, bv, out);

    // masked softmax
    max1_kernel<<<96, 256>>>();
    max2_kernel<<<1, 128>>>(96);
    expsum_kernel<<<96, 256>>>(out);
    norm_reset_kernel<<<NB_N, 256>>>(out);
    gsum_reset_kernel<<<1, 1>>>();
}

// round 9
// speedup vs baseline: 2.3394x; 2.3394x over previous
#include <cuda_runtime.h>
#include <cuda_fp16.h>
#include <math.h>

#define NN 100000
#define EE 3200000
#define DIN 128
#define HH 64
#define NEG_INF (-1e30f)

// ---------------- device scratch (zero-init at module load; self-restoring) ----------------
__device__ int   g_deg[NN];
__device__ int   g_fill[NN];
__device__ int   g_rowptr[NN + 1];
__device__ int   g_csr[EE];
__device__ float g_dinv[NN];
__device__ __half2 g_lin[(size_t)NN * 32];   // [N,64] fp16 messages (dinv-scaled lin)
__device__ float g_h[(size_t)NN * HH];       // [N,64] fp32 hidden
__device__ float g_s5[NN];
__device__ float g_logits[NN + 1];
__device__ float g_accum[HH];
__device__ float g_blockmax[128];
__device__ float g_gmax;
__device__ float g_gsum;

// ---------------- graph prep ----------------
__global__ void count_kernel(const int* __restrict__ rows) {
    int idx = blockIdx.x * blockDim.x + threadIdx.x;
    if (idx * 4 < EE) {
        int4 r = ((const int4*)rows)[idx];
        atomicAdd(&g_deg[r.x], 1);
        atomicAdd(&g_deg[r.y], 1);
        atomicAdd(&g_deg[r.z], 1);
        atomicAdd(&g_deg[r.w], 1);
    }
}

__global__ void scan_kernel() {
    __shared__ int sh[1024];
    int t = threadIdx.x;
    const int CH = (NN + 1023) / 1024;  // 98
    int beg = t * CH;
    int end = min(beg + CH, NN);
    int s = 0;
    for (int i = beg; i < end; i++) s += g_deg[i];
    sh[t] = s;
    __syncthreads();
    for (int off = 1; off < 1024; off <<= 1) {
        int v = (t >= off) ? sh[t - off] : 0;
        __syncthreads();
        sh[t] += v;
        __syncthreads();
    }
    int run = sh[t] - s;
    for (int i = beg; i < end; i++) {
        int d = g_deg[i];
        g_rowptr[i] = run;
        run += d;
        g_dinv[i] = rsqrtf((float)(d + 1));
    }
    if (t == 1023) g_rowptr[NN] = sh[1023];
}

__global__ void fill_kernel(const int* __restrict__ rows, const int* __restrict__ cols) {
    int idx = blockIdx.x * blockDim.x + threadIdx.x;
    if (idx * 4 < EE) {
        int4 r = ((const int4*)rows)[idx];
        int4 c = ((const int4*)cols)[idx];
        int p;
        p = g_rowptr[r.x] + atomicAdd(&g_fill[r.x], 1); g_csr[p] = c.x;
        p = g_rowptr[r.y] + atomicAdd(&g_fill[r.y], 1); g_csr[p] = c.y;
        p = g_rowptr[r.z] + atomicAdd(&g_fill[r.z], 1); g_csr[p] = c.z;
        p = g_rowptr[r.w] + atomicAdd(&g_fill[r.w], 1); g_csr[p] = c.w;
    }
}

// ---------------- GEMM: warp per row, shfl-broadcast; writes fp16 messages ----------------
// lin[row][2l..2l+1] = half(dinv[row] * sum_k Hin[row][k] * W[k][2l..2l+1])
template <int K>
__global__ __launch_bounds__(256) void gemm_rows(const float* __restrict__ Hin,
                                                 const float* __restrict__ W,
                                                 __half2* __restrict__ OutH) {
    __shared__ float2 Ws[K * 32];  // Ws[k*32+l] = (W[k][2l], W[k][2l+1])
    int tid = threadIdx.x;
    for (int i = tid; i < K * 32; i += 256) {
        int k = i >> 5, l = i & 31;
        Ws[i] = make_float2(W[k * 64 + 2 * l], W[k * 64 + 2 * l + 1]);
    }
    __syncthreads();

    int lane = tid & 31;
    int warp  = (blockIdx.x * 256 + tid) >> 5;
    int nwarp = (gridDim.x * 256) >> 5;

    for (int row = warp; row < NN; row += nwarp) {
        float a0 = 0.f, a1 = 0.f;
        if (K == 128) {
            float4 xr = ((const float4*)(Hin + (size_t)row * 128))[lane];
#pragma unroll
            for (int k = 0; k < 128; k++) {
                float xv = (k & 3) == 0 ? xr.x : (k & 3) == 1 ? xr.y : (k & 3) == 2 ? xr.z : xr.w;
                float xk = __shfl_sync(0xffffffffu, xv, k >> 2);
                float2 w = Ws[k * 32 + lane];
                a0 += xk * w.x;
                a1 += xk * w.y;
            }
        } else {  // K == 64
            float2 xr = ((const float2*)(Hin + (size_t)row * 64))[lane];
#pragma unroll
            for (int k = 0; k < 64; k++) {
                float xv = (k & 1) == 0 ? xr.x : xr.y;
                float xk = __shfl_sync(0xffffffffu, xv, k >> 1);
                float2 w = Ws[k * 32 + lane];
                a0 += xk * w.x;
                a1 += xk * w.y;
            }
        }
        float di = g_dinv[row];
        OutH[(size_t)row * 32 + lane] = __floats2half2_rn(di * a0, di * a1);
    }
}

// ---------------- aggregation v6: fp16 messages, 1 line/edge, quarter-warp per edge ----------------
// Row = 64 halves = 128B = ONE cache line. Lane covers 8 halves: l8 = lane&7, q = lane>>3.
// One warp LDG.128 gathers FOUR edges at once. fp32 accumulate.
__global__ __launch_bounds__(256) void agg16(const __half2* __restrict__ lin,
                                             const float* __restrict__ b,
                                             float* __restrict__ out, int relu) {
    int w = (blockIdx.x * blockDim.x + threadIdx.x) >> 5;
    int lane = threadIdx.x & 31;
    if (w >= NN) return;
    int q  = lane >> 3;    // 0..3 : edge slot within group of 4
    int l8 = lane & 7;     // 0..7 : 16B chunk within row
    const uint4* ls = (const uint4*)lin;   // 8 uint4 per row
    int beg = g_rowptr[w], end = g_rowptr[w + 1];
    int deg = end - beg;

    // preload up to 64 edge ids into registers
    int e0 = (lane      < deg) ? g_csr[beg + lane]      : 0;
    int e1 = (lane + 32 < deg) ? g_csr[beg + 32 + lane] : 0;

    float acc[8];
#pragma unroll
    for (int i = 0; i < 8; i++) acc[i] = 0.f;

    // self-loop on quarter 0
    if (q == 0) {
        uint4 v = ls[(size_t)w * 8 + l8];
#pragma unroll
        for (int i = 0; i < 4; i++) {
            float2 f = __half22float2(((const __half2*)&v)[i]);
            acc[2 * i]     += f.x;
            acc[2 * i + 1] += f.y;
        }
    }

    int np = min(deg, 64);
    int niter = (np + 3) >> 2;    // 4 edges per iteration
#pragma unroll 4
    for (int j = 0; j < niter; j++) {
        int slot = 4 * j + q;
        int c = (j < 8) ? __shfl_sync(0xffffffffu, e0, slot & 31)
                        : __shfl_sync(0xffffffffu, e1, slot & 31);
        if (slot < np) {
            uint4 v = ls[(size_t)c * 8 + l8];
#pragma unroll
            for (int i = 0; i < 4; i++) {
                float2 f = __half22float2(((const __half2*)&v)[i]);
                acc[2 * i]     += f.x;
                acc[2 * i + 1] += f.y;
            }
        }
    }
    // rare tail: deg > 64
    for (int e = beg + 64; e < end; e += 4) {
        int k = e + q;
        if (k < end) {
            int c = g_csr[k];
            uint4 v = ls[(size_t)c * 8 + l8];
#pragma unroll
            for (int i = 0; i < 4; i++) {
                float2 f = __half22float2(((const __half2*)&v)[i]);
                acc[2 * i]     += f.x;
                acc[2 * i + 1] += f.y;
            }
        }
    }

    // sum the 4 quarters (same columns, different edges)
#pragma unroll
    for (int i = 0; i < 8; i++) {
        acc[i] += __shfl_xor_sync(0xffffffffu, acc[i], 8);
        acc[i] += __shfl_xor_sync(0xffffffffu, acc[i], 16);
    }

    if (q == 0) {   // lanes 0..7 hold cols 8*l8 .. 8*l8+7
        float di = g_dinv[w];
        float4 bb0 = ((const float4*)b)[2 * l8];
        float4 bb1 = ((const float4*)b)[2 * l8 + 1];
        float4 o0, o1;
        o0.x = di * acc[0] + bb0.x;  o0.y = di * acc[1] + bb0.y;
        o0.z = di * acc[2] + bb0.z;  o0.w = di * acc[3] + bb0.w;
        o1.x = di * acc[4] + bb1.x;  o1.y = di * acc[5] + bb1.y;
        o1.z = di * acc[6] + bb1.z;  o1.w = di * acc[7] + bb1.w;
        if (relu) {
            o0.x = fmaxf(o0.x, 0.f); o0.y = fmaxf(o0.y, 0.f);
            o0.z = fmaxf(o0.z, 0.f); o0.w = fmaxf(o0.w, 0.f);
            o1.x = fmaxf(o1.x, 0.f); o1.y = fmaxf(o1.y, 0.f);
            o1.z = fmaxf(o1.z, 0.f); o1.w = fmaxf(o1.w, 0.f);
        }
        ((float4*)out)[(size_t)w * 16 + 2 * l8]     = o0;
        ((float4*)out)[(size_t)w * 16 + 2 * l8 + 1] = o1;
    }
}

// ---------------- heads ----------------
__global__ void mean_kernel(const float* __restrict__ h) {
    __shared__ float sacc[64];
    int t = threadIdx.x;
    if (t < 64) sacc[t] = 0.f;
    __syncthreads();
    int c = t & 63;
    float a = 0.f;
    for (int r = blockIdx.x * 4 + (t >> 6); r < NN; r += gridDim.x * 4)
        a += h[(size_t)r * 64 + c];
    atomicAdd(&sacc[c], a);
    __syncthreads();
    if (t < 64) atomicAdd(&g_accum[t], sacc[t]);
}

__global__ __launch_bounds__(256) void dot5_kernel(const float* __restrict__ h,
                                                   const float* __restrict__ W5) {
    int w = (blockIdx.x * blockDim.x + threadIdx.x) >> 5;
    int lane = threadIdx.x & 31;
    if (w >= NN) return;
    float d = h[(size_t)w * 64 + lane] * W5[lane] + h[(size_t)w * 64 + 32 + lane] * W5[lane + 32];
#pragma unroll
    for (int off = 16; off > 0; off >>= 1) d += __shfl_down_sync(0xffffffff, d, off);
    if (lane == 0) g_s5[w] = g_dinv[w] * d;
}

__global__ __launch_bounds__(256) void agg5_kernel(const float* __restrict__ b5,
                                                   const int* __restrict__ ready) {
    int w = (blockIdx.x * blockDim.x + threadIdx.x) >> 5;
    int lane = threadIdx.x & 31;
    if (w >= NN) return;
    int beg = g_rowptr[w], end = g_rowptr[w + 1];
    float acc = (lane == 0) ? g_s5[w] : 0.f;
    for (int e = beg + lane; e < end; e += 32) acc += g_s5[g_csr[e]];
#pragma unroll
    for (int off = 16; off > 0; off >>= 1) acc += __shfl_down_sync(0xffffffff, acc, off);
    if (lane == 0) {
        float logit = g_dinv[w] * acc + b5[0];
        g_logits[w] = (ready[w] != 0) ? logit : NEG_INF;
    }
}

__global__ void finalize_kernel(const float* __restrict__ Wdn, const float* __restrict__ bdn,
                                const float* __restrict__ Wv, const float* __restrict__ bv,
                                float* __restrict__ out) {
    __shared__ float s1[64], s2[64];
    int t = threadIdx.x;  // 64
    float xm = g_accum[t] * (1.0f / NN);
    s1[t] = xm * Wv[t];
    s2[t] = xm * Wdn[t];
    __syncthreads();
    if (t == 0) {
        float v = 0.f, pn = 0.f;
        for (int i = 0; i < 64; i++) { v += s1[i]; pn += s2[i]; }
        out[NN + 1]  = v + bv[0];
        g_logits[NN] = pn + bdn[0];
    }
}

// ---------------- masked softmax ----------------
__global__ void max1_kernel() {
    __shared__ float sm[256];
    float m = -3.4e38f;
    for (int i = blockIdx.x * blockDim.x + threadIdx.x; i < NN + 1; i += gridDim.x * blockDim.x)
        m = fmaxf(m, g_logits[i]);
    sm[threadIdx.x] = m;
    __syncthreads();
    for (int s = 128; s > 0; s >>= 1) {
        if (threadIdx.x < s) sm[threadIdx.x] = fmaxf(sm[threadIdx.x], sm[threadIdx.x + s]);
        __syncthreads();
    }
    if (threadIdx.x == 0) g_blockmax[blockIdx.x] = sm[0];
}

__global__ void max2_kernel(int nblocks) {
    __shared__ float sm[128];
    float m = -3.4e38f;
    for (int i = threadIdx.x; i < nblocks; i += 128) m = fmaxf(m, g_blockmax[i]);
    sm[threadIdx.x] = m;
    __syncthreads();
    for (int s = 64; s > 0; s >>= 1) {
        if (threadIdx.x < s) sm[threadIdx.x] = fmaxf(sm[threadIdx.x], sm[threadIdx.x + s]);
        __syncthreads();
    }
    if (threadIdx.x == 0) g_gmax = sm[0];
}

__global__ void expsum_kernel(float* __restrict__ out) {
    __shared__ float sm[256];
    float gm = g_gmax;
    float s = 0.f;
    for (int i = blockIdx.x * blockDim.x + threadIdx.x; i < NN + 1; i += gridDim.x * blockDim.x) {
        float e = expf(g_logits[i] - gm);
        out[i] = e;
        s += e;
    }
    sm[threadIdx.x] = s;
    __syncthreads();
    for (int st = 128; st > 0; st >>= 1) {
        if (threadIdx.x < st) sm[threadIdx.x] += sm[threadIdx.x + st];
        __syncthreads();
    }
    if (threadIdx.x == 0) atomicAdd(&g_gsum, sm[0]);
}

__global__ void norm_reset_kernel(float* __restrict__ out) {
    int i = blockIdx.x * blockDim.x + threadIdx.x;
    if (i <= NN) out[i] *= (1.0f / g_gsum);
    if (i < NN) { g_deg[i] = 0; g_fill[i] = 0; }
    if (i < HH) g_accum[i] = 0.f;
}
__global__ void gsum_reset_kernel() { g_gsum = 0.f; }

// ---------------- launch ----------------
extern "C" void kernel_launch(void* const* d_in, const int* in_sizes, int n_in,
                              void* d_out, int out_size) {
    (void)in_sizes; (void)n_in; (void)out_size;
    const float* x     = (const float*)d_in[0];
    const int*   ei    = (const int*)d_in[1];
    const int*   ready = (const int*)d_in[2];
    const float* W1 = (const float*)d_in[3];
    const float* b1 = (const float*)d_in[4];
    const float* W2 = (const float*)d_in[5];
    const float* b2 = (const float*)d_in[6];
    const float* W3 = (const float*)d_in[7];
    const float* b3 = (const float*)d_in[8];
    const float* W4 = (const float*)d_in[9];
    const float* b4 = (const float*)d_in[10];
    const float* W5 = (const float*)d_in[11];
    const float* b5 = (const float*)d_in[12];
    const float* Wdn = (const float*)d_in[13];
    const float* bdn = (const float*)d_in[14];
    const float* Wv  = (const float*)d_in[15];
    const float* bv  = (const float*)d_in[16];
    float* out = (float*)d_out;

    const int* rows = ei;
    const int* cols = ei + EE;

    const int NB_N  = (NN + 255) / 256;          // 391
    const int NB_E4 = (EE / 4 + 255) / 256;      // 3125
    const int NB_W  = (NN * 32 + 255) / 256;     // 12500 (warp per row)
    const int NB_G  = 1563;

    // graph prep
    count_kernel<<<NB_E4, 256>>>(rows);
    scan_kernel<<<1, 1024>>>();
    fill_kernel<<<NB_E4, 256>>>(rows, cols);

    // layer 1
    gemm_rows<DIN><<<NB_G, 256>>>(x, W1, g_lin);
    agg16<<<NB_W, 256>>>(g_lin, b1, g_h, 1);
    // layers 2-4
    gemm_rows<HH><<<NB_G, 256>>>(g_h, W2, g_lin);
    agg16<<<NB_W, 256>>>(g_lin, b2, g_h, 1);
    gemm_rows<HH><<<NB_G, 256>>>(g_h, W3, g_lin);
    agg16<<<NB_W, 256>>>(g_lin, b3, g_h, 1);
    gemm_rows<HH><<<NB_G, 256>>>(g_h, W4, g_lin);
    agg16<<<NB_W, 256>>>(g_lin, b4, g_h, 1);

    // heads
    mean_kernel<<<256, 256>>>(g_h);
    dot5_kernel<<<NB_W, 256>>>(g_h, W5);
    agg5_kernel<<<NB_W, 256>>>(b5, ready);
    finalize_kernel<<<1, 64>>>(Wdn, bdn, Wv, bv, out);

    // masked softmax
    max1_kernel<<<96, 256>>>();
    max2_kernel<<<1, 128>>>(96);
    expsum_kernel<<<96, 256>>>(out);
    norm_reset_kernel<<<NB_N, 256>>>(out);
    gsum_reset_kernel<<<1, 1>>>();
}